// round 1
// baseline (speedup 1.0000x reference)
#include <cuda_runtime.h>
#include <cstdint>

#define NN      12000
#define HID     32
#define TSTEPS  50
#define TM      128
#define KSPLIT  25
#define KITEM   480              // k per work item (15 chunks of 32)
#define NCHUNK  15
#define NBLK    94               // ceil(12000/128)
#define NITEMS  (NBLK * KSPLIT)  // 2350
#define GRID2   296              // 2 CTAs per SM (148 SMs)
#define STAGE_BYTES 20480        // A: 128*32*4 = 16384  +  B: 32*32*4 = 4096
#define SMEM_BYTES  (3 * STAGE_BYTES)

// Scratch (static device allocations are allowed; runtime alloc is not).
__device__ float g_suppT[HID * NN];           // support, transposed: [32][12000]
__device__ float g_part[KSPLIT * NN * HID];   // split-K partials (deterministic)

// ---------------------------------------------------------------------------
// Kernel 1: support = [z | a_t] @ W, written transposed ([col][row]) so the
// GEMM's B operand has contiguous k. One warp per row; W staged in smem.
// ---------------------------------------------------------------------------
__global__ void support_kernel(const float* __restrict__ t,
                               const float* __restrict__ z,
                               const float* __restrict__ treat,
                               const float* __restrict__ W) {
    __shared__ float Ws[33 * 32];
    int tid = threadIdx.x;
    for (int i = tid; i < 33 * 32; i += blockDim.x) Ws[i] = W[i];
    __syncthreads();

    int a_idx = (int)(t[0] * (float)(TSTEPS - 1));   // trunc-toward-zero == jnp astype
    a_idx = min(max(a_idx, 0), TSTEPS - 1);

    int lane = tid & 31;
    int warp = tid >> 5;
    int row  = blockIdx.x * 8 + warp;
    if (row >= NN) return;

    float zv = z[row * 32 + lane];
    float at = treat[row * TSTEPS + a_idx];
    float acc = at * Ws[32 * 32 + lane];
#pragma unroll
    for (int k = 0; k < 32; k++) {
        float zk = __shfl_sync(0xffffffffu, zv, k);
        acc = fmaf(zk, Ws[k * 32 + lane], acc);
    }
    g_suppT[lane * NN + row] = acc;
}

// ---------------------------------------------------------------------------
// Kernel 2: split-K GEMM. C_part[kc] = adj[block rows, k-range] @ support.
// f32x2 FFMA2 inner loop, k-paired accumulators, cp.async 3-stage pipeline,
// XOR-swizzled smem.
// ---------------------------------------------------------------------------
__device__ __forceinline__ void stage_load(uint32_t smem_u, int stage,
                                           const float* __restrict__ adj,
                                           int row0, int gk, int tid) {
    uint32_t a_base = smem_u + stage * STAGE_BYTES;
    uint32_t b_base = a_base + 16384;

    // A tile: 128 rows x 32 k-floats. Thread = one row, 8 x 16B chunks.
    int row = row0 + tid;
    const float* asrc = adj + (long long)row * NN + gk;
    uint32_t adst = a_base + tid * 128;
    int sw = (tid >> 3) & 7;
    int sz = (row < NN) ? 16 : 0;   // zero-fill rows past N
#pragma unroll
    for (int q = 0; q < 8; q++) {
        uint32_t dst = adst + (uint32_t)((q ^ sw) << 4);
        asm volatile("cp.async.cg.shared.global [%0], [%1], 16, %2;\n"
                     :: "r"(dst), "l"(asrc + q * 4), "r"(sz));
    }

    // B tile: 32 cols x 32 k-floats from transposed support. 2 chunks/thread.
    int col = tid >> 2;
    int swb = (col >> 2) & 7;
    const float* bsrc = g_suppT + (long long)col * NN + gk;
    uint32_t bdst = b_base + col * 128;
    int q0 = (tid & 3) * 2;
#pragma unroll
    for (int e = 0; e < 2; e++) {
        int q = q0 + e;
        uint32_t dst = bdst + (uint32_t)((q ^ swb) << 4);
        asm volatile("cp.async.cg.shared.global [%0], [%1], 16;\n"
                     :: "r"(dst), "l"(bsrc + q * 4));
    }
}

__global__ void __launch_bounds__(128, 2)
gemm_kernel(const float* __restrict__ adj) {
    extern __shared__ float smem[];
    uint32_t smem_u = (uint32_t)__cvta_generic_to_shared(smem);
    int tid = threadIdx.x;
    int cg = tid & 7;     // col group: cols cg*4 .. cg*4+3
    int rg = tid >> 3;    // row group: rows rg*8 .. rg*8+7

    for (int item = blockIdx.x; item < NITEMS; item += GRID2) {
        int blk  = item / KSPLIT;
        int kc   = item - blk * KSPLIT;
        int row0 = blk * TM;
        int k0   = kc * KITEM;

        // f32x2 accumulators: lo = sum over even k, hi = sum over odd k
        unsigned long long acc[8][4];
#pragma unroll
        for (int i = 0; i < 8; i++)
#pragma unroll
            for (int j = 0; j < 4; j++) acc[i][j] = 0ull;

        stage_load(smem_u, 0, adj, row0, k0, tid);
        asm volatile("cp.async.commit_group;\n" ::: "memory");
        stage_load(smem_u, 1, adj, row0, k0 + 32, tid);
        asm volatile("cp.async.commit_group;\n" ::: "memory");

        for (int c = 0; c < NCHUNK; c++) {
            asm volatile("cp.async.wait_group 1;\n" ::: "memory");
            __syncthreads();
            if (c + 2 < NCHUNK)
                stage_load(smem_u, (c + 2) % 3, adj, row0, k0 + (c + 2) * 32, tid);
            asm volatile("cp.async.commit_group;\n" ::: "memory");

            int s = c % 3;
            uint32_t a_base = smem_u + s * STAGE_BYTES;
            uint32_t b_base = a_base + 16384;
#pragma unroll
            for (int kq = 0; kq < 8; kq++) {
                unsigned long long areg[8][2], breg[4][2];
#pragma unroll
                for (int i = 0; i < 8; i++) {
                    int row = rg * 8 + i;
                    uint32_t addr = a_base + row * 128 +
                                    (uint32_t)(((kq ^ ((row >> 3) & 7))) << 4);
                    asm volatile("ld.shared.v2.u64 {%0,%1}, [%2];\n"
                                 : "=l"(areg[i][0]), "=l"(areg[i][1]) : "r"(addr));
                }
#pragma unroll
                for (int j = 0; j < 4; j++) {
                    int col = cg * 4 + j;
                    uint32_t addr = b_base + col * 128 +
                                    (uint32_t)(((kq ^ ((col >> 2) & 7))) << 4);
                    asm volatile("ld.shared.v2.u64 {%0,%1}, [%2];\n"
                                 : "=l"(breg[j][0]), "=l"(breg[j][1]) : "r"(addr));
                }
#pragma unroll
                for (int i = 0; i < 8; i++)
#pragma unroll
                    for (int j = 0; j < 4; j++) {
                        asm volatile("fma.rn.f32x2 %0, %1, %2, %0;\n"
                                     : "+l"(acc[i][j]) : "l"(areg[i][0]), "l"(breg[j][0]));
                        asm volatile("fma.rn.f32x2 %0, %1, %2, %0;\n"
                                     : "+l"(acc[i][j]) : "l"(areg[i][1]), "l"(breg[j][1]));
                    }
            }
        }

        // horizontal combine (even-k + odd-k) and store this split's partial
        float* part = g_part + (long long)kc * (NN * HID);
#pragma unroll
        for (int i = 0; i < 8; i++) {
            int row = row0 + rg * 8 + i;
            if (row < NN) {
                float4 v;
                v.x = __uint_as_float((uint32_t)acc[i][0]) +
                      __uint_as_float((uint32_t)(acc[i][0] >> 32));
                v.y = __uint_as_float((uint32_t)acc[i][1]) +
                      __uint_as_float((uint32_t)(acc[i][1] >> 32));
                v.z = __uint_as_float((uint32_t)acc[i][2]) +
                      __uint_as_float((uint32_t)(acc[i][2] >> 32));
                v.w = __uint_as_float((uint32_t)acc[i][3]) +
                      __uint_as_float((uint32_t)(acc[i][3] >> 32));
                *(float4*)(part + (long long)row * HID + cg * 4) = v;
            }
        }
    }
}

// ---------------------------------------------------------------------------
// Kernel 3: out = relu(sum_kc part[kc] + b)  (deterministic split-K reduce)
// ---------------------------------------------------------------------------
__global__ void reduce_relu_kernel(float* __restrict__ out,
                                   const float* __restrict__ b) {
    int i4 = blockIdx.x * blockDim.x + threadIdx.x;   // float4 index
    if (i4 >= NN * HID / 4) return;
    const float4* p = (const float4*)g_part;
    float4 s = ((const float4*)b)[i4 & 7];
#pragma unroll
    for (int kc = 0; kc < KSPLIT; kc++) {
        float4 v = p[(long long)kc * (NN * HID / 4) + i4];
        s.x += v.x; s.y += v.y; s.z += v.z; s.w += v.w;
    }
    float4 r;
    r.x = fmaxf(s.x, 0.f);
    r.y = fmaxf(s.y, 0.f);
    r.z = fmaxf(s.z, 0.f);
    r.w = fmaxf(s.w, 0.f);
    ((float4*)out)[i4] = r;
}

// ---------------------------------------------------------------------------
extern "C" void kernel_launch(void* const* d_in, const int* in_sizes, int n_in,
                              void* d_out, int out_size) {
    (void)in_sizes; (void)n_in; (void)out_size;
    const float* t     = (const float*)d_in[0];
    const float* z     = (const float*)d_in[1];
    const float* adj   = (const float*)d_in[2];
    const float* treat = (const float*)d_in[3];
    const float* W     = (const float*)d_in[4];
    const float* b     = (const float*)d_in[5];
    float* out = (float*)d_out;

    cudaFuncSetAttribute(gemm_kernel,
                         cudaFuncAttributeMaxDynamicSharedMemorySize, SMEM_BYTES);

    support_kernel<<<(NN + 7) / 8, 256>>>(t, z, treat, W);
    gemm_kernel<<<GRID2, 128, SMEM_BYTES>>>(adj);
    reduce_relu_kernel<<<(NN * HID / 4 + 255) / 256, 256>>>(out, b);
}

// round 3
// speedup vs baseline: 2.3236x; 2.3236x over previous
#include <cuda_runtime.h>
#include <cstdint>

#define NN      12000
#define HID     32
#define TSTEPS  50
#define TM      128
#define KSPLIT  3
#define KITEM   4000             // K per work item (KSPLIT*KITEM == NN)
#define NCHUNK  125              // KITEM / 32
#define NBLK    94               // ceil(12000/128)
#define NITEMS  (NBLK * KSPLIT)  // 282 CTAs, one item each
#define NSTAGES 3
#define STAGE_BYTES 20480        // A: 128*32*4 = 16384  +  B: 32*32*4 = 4096
#define SMEM_REQ (NSTAGES * STAGE_BYTES)

__device__ float g_suppT[HID * NN];           // support^T: [32][12000], tf32-rounded
__device__ float g_part[KSPLIT * NN * HID];   // split-K partials (deterministic)

// ---------------------------------------------------------------------------
// Kernel 1: support = [z | a_t] @ W, transposed + tf32-rounded output.
// ---------------------------------------------------------------------------
__global__ void support_kernel(const float* __restrict__ t,
                               const float* __restrict__ z,
                               const float* __restrict__ treat,
                               const float* __restrict__ W) {
    __shared__ float Ws[33 * 32];
    __shared__ float S[8][36];     // stride 36 -> conflict-free transpose
    int tid = threadIdx.x;
    for (int i = tid; i < 33 * 32; i += blockDim.x) Ws[i] = W[i];
    __syncthreads();

    int a_idx = (int)(t[0] * (float)(TSTEPS - 1));
    a_idx = min(max(a_idx, 0), TSTEPS - 1);

    int lane = tid & 31;
    int warp = tid >> 5;
    int row  = blockIdx.x * 8 + warp;   // grid=1500, 1500*8 == 12000 exactly

    float zv = z[row * 32 + lane];
    float at = treat[row * TSTEPS + a_idx];
    float acc = at * Ws[32 * 32 + lane];
#pragma unroll
    for (int k = 0; k < 32; k++) {
        float zk = __shfl_sync(0xffffffffu, zv, k);
        acc = fmaf(zk, Ws[k * 32 + lane], acc);
    }
    uint32_t bits;
    asm("cvt.rna.tf32.f32 %0, %1;" : "=r"(bits) : "f"(acc));
    S[warp][lane] = __uint_as_float(bits);
    __syncthreads();

    // coalesced-ish transposed store: col-major [col][row]
    int col = tid >> 3;
    int rl  = tid & 7;
    g_suppT[col * NN + blockIdx.x * 8 + rl] = S[rl][col];
}

// ---------------------------------------------------------------------------
// Kernel 2: tf32 mma.sync GEMM. 256 thr, 8 warps x (m16,n32), 3-stage cp.async.
// ---------------------------------------------------------------------------
__device__ __forceinline__ void load_stage(char* stage, const float* __restrict__ adj,
                                           int row0, int gk, int tid) {
    // A: 128 rows x 128 B. 2 threads per row, 4 x 16B each. Swizzle q ^ (row&7).
    {
        int r = tid >> 1;
        int h = tid & 1;
        const float* src = adj + (long long)(row0 + r) * NN + gk;
        uint32_t dst = (uint32_t)__cvta_generic_to_shared(stage) + r * 128;
        int sw = r & 7;
        int sz = (row0 + r < NN) ? 16 : 0;
#pragma unroll
        for (int i = 0; i < 4; i++) {
            int q = h * 4 + i;
            asm volatile("cp.async.cg.shared.global [%0], [%1], 16, %2;\n"
                         :: "r"(dst + (uint32_t)((q ^ sw) << 4)),
                            "l"(src + q * 4), "r"(sz));
        }
    }
    // B: 32 cols x 128 B. 1 x 16B per thread.
    {
        int c = tid >> 3;
        int q = tid & 7;
        const float* src = g_suppT + (long long)c * NN + gk + q * 4;
        uint32_t dst = (uint32_t)__cvta_generic_to_shared(stage) + 16384 +
                       c * 128 + (uint32_t)((q ^ (c & 7)) << 4);
        asm volatile("cp.async.cg.shared.global [%0], [%1], 16;\n"
                     :: "r"(dst), "l"(src));
    }
}

__global__ void __launch_bounds__(256, 2)
gemm_mma_kernel(const float* __restrict__ adj) {
    extern __shared__ char dsm[];
    int tid  = threadIdx.x;
    int warp = tid >> 5;
    int lane = tid & 31;
    int g    = lane >> 2;    // groupID
    int tg   = lane & 3;     // threadID in group

    int blk  = blockIdx.x / KSPLIT;
    int kc   = blockIdx.x - blk * KSPLIT;
    int row0 = blk * TM;
    int k0   = kc * KITEM;

    float acc[4][4];         // [ntile][c0..c3]
#pragma unroll
    for (int n = 0; n < 4; n++)
#pragma unroll
        for (int i = 0; i < 4; i++) acc[n][i] = 0.f;

    // per-thread fragment base offsets (bytes) within a stage
    //   A row r = warp*16 + g  (r & 7 == g), byte-in-chunk = tg*4
    const uint32_t aoff = (uint32_t)(warp * 16 + g) * 128 + tg * 4;
    //   B col c = nt*8 + g     (c & 7 == g)
    const uint32_t boff = 16384u + (uint32_t)g * 128 + tg * 4;

    load_stage(dsm, adj, row0, k0, tid);
    asm volatile("cp.async.commit_group;\n" ::: "memory");
    load_stage(dsm + STAGE_BYTES, adj, row0, k0 + 32, tid);
    asm volatile("cp.async.commit_group;\n" ::: "memory");

    for (int c = 0; c < NCHUNK; c++) {
        asm volatile("cp.async.wait_group 1;\n" ::: "memory");
        __syncthreads();

        if (c + 2 < NCHUNK)
            load_stage(dsm + ((c + 2) % NSTAGES) * STAGE_BYTES, adj,
                       row0, k0 + (c + 2) * 32, tid);
        asm volatile("cp.async.commit_group;\n" ::: "memory");

        const char* st = dsm + (c % NSTAGES) * STAGE_BYTES;
#pragma unroll
        for (int ks = 0; ks < 4; ks++) {
            uint32_t q0 = (uint32_t)(((2 * ks) ^ g) << 4);
            uint32_t q1 = (uint32_t)(((2 * ks + 1) ^ g) << 4);

            uint32_t a0 = *(const uint32_t*)(st + aoff + q0);
            uint32_t a2 = *(const uint32_t*)(st + aoff + q1);
            uint32_t a1 = *(const uint32_t*)(st + aoff + 1024 + q0);  // row +8
            uint32_t a3 = *(const uint32_t*)(st + aoff + 1024 + q1);
#pragma unroll
            for (int nt = 0; nt < 4; nt++) {
                uint32_t b0 = *(const uint32_t*)(st + boff + nt * 1024 + q0);
                uint32_t b1 = *(const uint32_t*)(st + boff + nt * 1024 + q1);
                asm volatile(
                    "mma.sync.aligned.m16n8k8.row.col.f32.tf32.tf32.f32 "
                    "{%0,%1,%2,%3}, {%4,%5,%6,%7}, {%8,%9}, {%0,%1,%2,%3};\n"
                    : "+f"(acc[nt][0]), "+f"(acc[nt][1]),
                      "+f"(acc[nt][2]), "+f"(acc[nt][3])
                    : "r"(a0), "r"(a1), "r"(a2), "r"(a3), "r"(b0), "r"(b1));
            }
        }
    }

    // epilogue: store split-K partial. c0/c1: (row, 2tg..2tg+1); c2/c3: row+8.
    float* part = g_part + (long long)kc * (NN * HID);
    int r_lo = row0 + warp * 16 + g;
    int r_hi = r_lo + 8;
#pragma unroll
    for (int nt = 0; nt < 4; nt++) {
        int colb = nt * 8 + 2 * tg;
        if (r_lo < NN)
            *(float2*)(part + (long long)r_lo * HID + colb) =
                make_float2(acc[nt][0], acc[nt][1]);
        if (r_hi < NN)
            *(float2*)(part + (long long)r_hi * HID + colb) =
                make_float2(acc[nt][2], acc[nt][3]);
    }
}

// ---------------------------------------------------------------------------
// Kernel 3: out = relu(sum_kc part[kc] + b)
// ---------------------------------------------------------------------------
__global__ void reduce_relu_kernel(float* __restrict__ out,
                                   const float* __restrict__ b) {
    int i4 = blockIdx.x * blockDim.x + threadIdx.x;
    if (i4 >= NN * HID / 4) return;
    const float4* p = (const float4*)g_part;
    float4 s = ((const float4*)b)[i4 & 7];
#pragma unroll
    for (int kc = 0; kc < KSPLIT; kc++) {
        float4 v = p[(long long)kc * (NN * HID / 4) + i4];
        s.x += v.x; s.y += v.y; s.z += v.z; s.w += v.w;
    }
    float4 r;
    r.x = fmaxf(s.x, 0.f);
    r.y = fmaxf(s.y, 0.f);
    r.z = fmaxf(s.z, 0.f);
    r.w = fmaxf(s.w, 0.f);
    ((float4*)out)[i4] = r;
}

// ---------------------------------------------------------------------------
extern "C" void kernel_launch(void* const* d_in, const int* in_sizes, int n_in,
                              void* d_out, int out_size) {
    (void)in_sizes; (void)n_in; (void)out_size;
    const float* t     = (const float*)d_in[0];
    const float* z     = (const float*)d_in[1];
    const float* adj   = (const float*)d_in[2];
    const float* treat = (const float*)d_in[3];
    const float* W     = (const float*)d_in[4];
    const float* b     = (const float*)d_in[5];
    float* out = (float*)d_out;

    cudaFuncSetAttribute(gemm_mma_kernel,
                         cudaFuncAttributeMaxDynamicSharedMemorySize, SMEM_REQ);

    support_kernel<<<NN / 8, 256>>>(t, z, treat, W);
    gemm_mma_kernel<<<NITEMS, 256, SMEM_REQ>>>(adj);
    reduce_relu_kernel<<<(NN * HID / 4 + 255) / 256, 256>>>(out, b);
}

// round 4
// speedup vs baseline: 2.3309x; 1.0031x over previous
#include <cuda_runtime.h>
#include <cstdint>

#define NN      12000
#define HID     32
#define TSTEPS  50
#define TM      128
#define KSPLIT  3
#define KITEM   4000             // K per work item (KSPLIT*KITEM == NN)
#define NCHUNK  125              // KITEM / 32
#define NBLK    94               // ceil(12000/128)
#define NITEMS  (NBLK * KSPLIT)  // 282 CTAs, one item each
#define NSTAGES 5
#define STAGE_BYTES 20480        // A: 128*32*4 = 16384  +  B: 32*32*4 = 4096
#define SMEM_REQ (NSTAGES * STAGE_BYTES)

__device__ float g_suppT[HID * NN];           // support^T: [32][12000], tf32-rounded
__device__ float g_part[KSPLIT * NN * HID];   // split-K partials (deterministic)

// ---------------------------------------------------------------------------
// Kernel 1: support = [z | a_t] @ W, transposed + tf32-rounded output.
// 4 rows per warp (4 independent FMA chains), 32 rows per block.
// ---------------------------------------------------------------------------
__global__ void support_kernel(const float* __restrict__ t,
                               const float* __restrict__ z,
                               const float* __restrict__ treat,
                               const float* __restrict__ W) {
    __shared__ float Ws[33 * 32];
    __shared__ float S[32][33];    // stride 33 -> conflict-free transpose
    int tid = threadIdx.x;
    for (int i = tid; i < 33 * 32; i += blockDim.x) Ws[i] = W[i];
    __syncthreads();

    int a_idx = (int)(t[0] * (float)(TSTEPS - 1));
    a_idx = min(max(a_idx, 0), TSTEPS - 1);

    int lane = tid & 31;
    int warp = tid >> 5;
    int row0 = blockIdx.x * 32;         // grid = 375, 375*32 == 12000
    int r0   = warp * 4;                // warp's 4 rows within block

    float zv[4], acc[4];
#pragma unroll
    for (int j = 0; j < 4; j++) {
        int row = row0 + r0 + j;
        zv[j]  = z[row * 32 + lane];
        acc[j] = treat[row * TSTEPS + a_idx] * Ws[32 * 32 + lane];
    }
#pragma unroll
    for (int k = 0; k < 32; k++) {
        float w = Ws[k * 32 + lane];
#pragma unroll
        for (int j = 0; j < 4; j++) {
            float zk = __shfl_sync(0xffffffffu, zv[j], k);
            acc[j] = fmaf(zk, w, acc[j]);
        }
    }
#pragma unroll
    for (int j = 0; j < 4; j++) {
        uint32_t bits;
        asm("cvt.rna.tf32.f32 %0, %1;" : "=r"(bits) : "f"(acc[j]));
        S[r0 + j][lane] = __uint_as_float(bits);
    }
    __syncthreads();

    // coalesced transposed store: 1024 elems, 4 per thread
#pragma unroll
    for (int j = 0; j < 4; j++) {
        int idx = tid + 256 * j;
        int col = idx >> 5;
        int r   = idx & 31;
        g_suppT[col * NN + row0 + r] = S[r][col];
    }
}

// ---------------------------------------------------------------------------
// Kernel 2: tf32 mma.sync GEMM. 256 thr, 8 warps x (m16,n32), 5-stage cp.async.
// ---------------------------------------------------------------------------
__device__ __forceinline__ void load_stage(char* stage, const float* __restrict__ adj,
                                           int row0, int gk, int tid) {
    // A: 128 rows x 128 B. 2 threads per row, 4 x 16B each. Swizzle q ^ (row&7).
    {
        int r = tid >> 1;
        int h = tid & 1;
        const float* src = adj + (long long)(row0 + r) * NN + gk;
        uint32_t dst = (uint32_t)__cvta_generic_to_shared(stage) + r * 128;
        int sw = r & 7;
        int sz = (row0 + r < NN) ? 16 : 0;
#pragma unroll
        for (int i = 0; i < 4; i++) {
            int q = h * 4 + i;
            asm volatile("cp.async.cg.shared.global.L2::256B [%0], [%1], 16, %2;\n"
                         :: "r"(dst + (uint32_t)((q ^ sw) << 4)),
                            "l"(src + q * 4), "r"(sz));
        }
    }
    // B: 32 cols x 128 B. 1 x 16B per thread.
    {
        int c = tid >> 3;
        int q = tid & 7;
        const float* src = g_suppT + (long long)c * NN + gk + q * 4;
        uint32_t dst = (uint32_t)__cvta_generic_to_shared(stage) + 16384 +
                       c * 128 + (uint32_t)((q ^ (c & 7)) << 4);
        asm volatile("cp.async.cg.shared.global.L2::256B [%0], [%1], 16;\n"
                     :: "r"(dst), "l"(src));
    }
}

__global__ void __launch_bounds__(256, 2)
gemm_mma_kernel(const float* __restrict__ adj) {
    extern __shared__ char dsm[];
    int tid  = threadIdx.x;
    int warp = tid >> 5;
    int lane = tid & 31;
    int g    = lane >> 2;    // groupID
    int tg   = lane & 3;     // threadID in group

    int blk  = blockIdx.x / KSPLIT;
    int kc   = blockIdx.x - blk * KSPLIT;
    int row0 = blk * TM;
    int k0   = kc * KITEM;

    float acc[4][4];         // [ntile][c0..c3]
#pragma unroll
    for (int n = 0; n < 4; n++)
#pragma unroll
        for (int i = 0; i < 4; i++) acc[n][i] = 0.f;

    // per-thread fragment base offsets (bytes) within a stage
    const uint32_t aoff = (uint32_t)(warp * 16 + g) * 128 + tg * 4;
    const uint32_t boff = 16384u + (uint32_t)g * 128 + tg * 4;

    // prologue: fill 4 of 5 stages
#pragma unroll
    for (int p = 0; p < NSTAGES - 1; p++) {
        load_stage(dsm + p * STAGE_BYTES, adj, row0, k0 + p * 32, tid);
        asm volatile("cp.async.commit_group;\n" ::: "memory");
    }

    for (int c = 0; c < NCHUNK; c++) {
        asm volatile("cp.async.wait_group %0;\n" :: "n"(NSTAGES - 2) : "memory");
        __syncthreads();

        if (c + NSTAGES - 1 < NCHUNK)
            load_stage(dsm + ((c + NSTAGES - 1) % NSTAGES) * STAGE_BYTES, adj,
                       row0, k0 + (c + NSTAGES - 1) * 32, tid);
        asm volatile("cp.async.commit_group;\n" ::: "memory");

        const char* st = dsm + (c % NSTAGES) * STAGE_BYTES;
#pragma unroll
        for (int ks = 0; ks < 4; ks++) {
            uint32_t q0 = (uint32_t)(((2 * ks) ^ g) << 4);
            uint32_t q1 = (uint32_t)(((2 * ks + 1) ^ g) << 4);

            uint32_t a0 = *(const uint32_t*)(st + aoff + q0);
            uint32_t a2 = *(const uint32_t*)(st + aoff + q1);
            uint32_t a1 = *(const uint32_t*)(st + aoff + 1024 + q0);  // row +8
            uint32_t a3 = *(const uint32_t*)(st + aoff + 1024 + q1);
#pragma unroll
            for (int nt = 0; nt < 4; nt++) {
                uint32_t b0 = *(const uint32_t*)(st + boff + nt * 1024 + q0);
                uint32_t b1 = *(const uint32_t*)(st + boff + nt * 1024 + q1);
                asm volatile(
                    "mma.sync.aligned.m16n8k8.row.col.f32.tf32.tf32.f32 "
                    "{%0,%1,%2,%3}, {%4,%5,%6,%7}, {%8,%9}, {%0,%1,%2,%3};\n"
                    : "+f"(acc[nt][0]), "+f"(acc[nt][1]),
                      "+f"(acc[nt][2]), "+f"(acc[nt][3])
                    : "r"(a0), "r"(a1), "r"(a2), "r"(a3), "r"(b0), "r"(b1));
            }
        }
    }

    // epilogue: store split-K partial
    float* part = g_part + (long long)kc * (NN * HID);
    int r_lo = row0 + warp * 16 + g;
    int r_hi = r_lo + 8;
#pragma unroll
    for (int nt = 0; nt < 4; nt++) {
        int colb = nt * 8 + 2 * tg;
        if (r_lo < NN)
            *(float2*)(part + (long long)r_lo * HID + colb) =
                make_float2(acc[nt][0], acc[nt][1]);
        if (r_hi < NN)
            *(float2*)(part + (long long)r_hi * HID + colb) =
                make_float2(acc[nt][2], acc[nt][3]);
    }
}

// ---------------------------------------------------------------------------
// Kernel 3: out = relu(sum_kc part[kc] + b)
// ---------------------------------------------------------------------------
__global__ void reduce_relu_kernel(float* __restrict__ out,
                                   const float* __restrict__ b) {
    int i4 = blockIdx.x * blockDim.x + threadIdx.x;
    if (i4 >= NN * HID / 4) return;
    const float4* p = (const float4*)g_part;
    float4 s = ((const float4*)b)[i4 & 7];
#pragma unroll
    for (int kc = 0; kc < KSPLIT; kc++) {
        float4 v = p[(long long)kc * (NN * HID / 4) + i4];
        s.x += v.x; s.y += v.y; s.z += v.z; s.w += v.w;
    }
    float4 r;
    r.x = fmaxf(s.x, 0.f);
    r.y = fmaxf(s.y, 0.f);
    r.z = fmaxf(s.z, 0.f);
    r.w = fmaxf(s.w, 0.f);
    ((float4*)out)[i4] = r;
}

// ---------------------------------------------------------------------------
extern "C" void kernel_launch(void* const* d_in, const int* in_sizes, int n_in,
                              void* d_out, int out_size) {
    (void)in_sizes; (void)n_in; (void)out_size;
    const float* t     = (const float*)d_in[0];
    const float* z     = (const float*)d_in[1];
    const float* adj   = (const float*)d_in[2];
    const float* treat = (const float*)d_in[3];
    const float* W     = (const float*)d_in[4];
    const float* b     = (const float*)d_in[5];
    float* out = (float*)d_out;

    cudaFuncSetAttribute(gemm_mma_kernel,
                         cudaFuncAttributeMaxDynamicSharedMemorySize, SMEM_REQ);

    support_kernel<<<NN / 32, 256>>>(t, z, treat, W);
    gemm_mma_kernel<<<NITEMS, 256, SMEM_REQ>>>(adj);
    reduce_relu_kernel<<<(NN * HID / 4 + 255) / 256, 256>>>(out, b);
}

// round 5
// speedup vs baseline: 3.2404x; 1.3902x over previous
#include <cuda_runtime.h>
#include <cstdint>

#define NN      12000
#define HID     32
#define TSTEPS  50
#define TM      128
#define KSPLIT  3
#define KITEM   4000             // K per work item (KSPLIT*KITEM == NN)
#define NCHUNK  125              // KITEM / 32
#define NBLK    94               // ceil(12000/128)
#define NITEMS  (NBLK * KSPLIT)  // 282 CTAs, one item each
#define NSTAGES 5
#define STAGE_BYTES 20480        // A: 128*32*4 = 16384  +  B: 32*32*4 = 4096
#define SMEM_REQ (NSTAGES * STAGE_BYTES)

__device__ float g_suppT[HID * NN];           // support^T: [32][12000], tf32-rounded
__device__ float g_part[KSPLIT * NN * HID];   // split-K partials (deterministic)

// ---------------------------------------------------------------------------
// Kernel 1: support = [z | a_t] @ W, transposed + tf32-rounded output.
// ---------------------------------------------------------------------------
__global__ void support_kernel(const float* __restrict__ t,
                               const float* __restrict__ z,
                               const float* __restrict__ treat,
                               const float* __restrict__ W) {
    __shared__ float Ws[33 * 32];
    __shared__ float S[32][33];    // stride 33 -> conflict-free transpose
    int tid = threadIdx.x;
    for (int i = tid; i < 33 * 32; i += blockDim.x) Ws[i] = W[i];
    __syncthreads();

    int a_idx = (int)(t[0] * (float)(TSTEPS - 1));
    a_idx = min(max(a_idx, 0), TSTEPS - 1);

    int lane = tid & 31;
    int warp = tid >> 5;
    int row0 = blockIdx.x * 32;         // grid = 375, 375*32 == 12000
    int r0   = warp * 4;                // warp's 4 rows within block

    float zv[4], acc[4];
#pragma unroll
    for (int j = 0; j < 4; j++) {
        int row = row0 + r0 + j;
        zv[j]  = z[row * 32 + lane];
        acc[j] = treat[row * TSTEPS + a_idx] * Ws[32 * 32 + lane];
    }
#pragma unroll
    for (int k = 0; k < 32; k++) {
        float w = Ws[k * 32 + lane];
#pragma unroll
        for (int j = 0; j < 4; j++) {
            float zk = __shfl_sync(0xffffffffu, zv[j], k);
            acc[j] = fmaf(zk, w, acc[j]);
        }
    }
#pragma unroll
    for (int j = 0; j < 4; j++) {
        uint32_t bits;
        asm("cvt.rna.tf32.f32 %0, %1;" : "=r"(bits) : "f"(acc[j]));
        S[r0 + j][lane] = __uint_as_float(bits);
    }
    __syncthreads();

#pragma unroll
    for (int j = 0; j < 4; j++) {
        int idx = tid + 256 * j;
        int col = idx >> 5;
        int r   = idx & 31;
        g_suppT[col * NN + row0 + r] = S[r][col];
    }
}

// ---------------------------------------------------------------------------
// Kernel 2: tf32 mma.sync GEMM. 256 thr, 8 warps x (m16,n32), 5-stage cp.async.
// Load lane map is LINE-COMPLETE per warp-op: row = tid>>3, chunk = tid&7, so
// every touched 128B line gets all 8x16B requests in one warp-op (whole
// sectors -> no doubled LTS transactions).
// ---------------------------------------------------------------------------
__device__ __forceinline__ void load_stage(char* stage, const float* __restrict__ adj,
                                           int row0, int gk, int tid) {
    int q  = tid & 7;              // 16B chunk within 128B row-chunk
    int rb = tid >> 3;             // 0..31
    uint32_t sbase = (uint32_t)__cvta_generic_to_shared(stage);

    // A: 128 rows x 128 B; 4 iterations of 32 rows, each warp-op = 4 full lines
#pragma unroll
    for (int i = 0; i < 4; i++) {
        int r = i * 32 + rb;
        const float* src = adj + (long long)(row0 + r) * NN + gk + q * 4;
        uint32_t dst = sbase + r * 128 + (uint32_t)((q ^ (r & 7)) << 4);
        int sz = (row0 + r < NN) ? 16 : 0;
        asm volatile("cp.async.cg.shared.global.L2::256B [%0], [%1], 16, %2;\n"
                     :: "r"(dst), "l"(src), "r"(sz));
    }
    // B: 32 cols x 128 B; one 16B chunk per thread, warp-op = 4 full lines
    {
        int c = rb;
        const float* src = g_suppT + (long long)c * NN + gk + q * 4;
        uint32_t dst = sbase + 16384 + c * 128 + (uint32_t)((q ^ (c & 7)) << 4);
        asm volatile("cp.async.cg.shared.global.L2::256B [%0], [%1], 16;\n"
                     :: "r"(dst), "l"(src));
    }
}

__global__ void __launch_bounds__(256, 2)
gemm_mma_kernel(const float* __restrict__ adj) {
    extern __shared__ char dsm[];
    int tid  = threadIdx.x;
    int warp = tid >> 5;
    int lane = tid & 31;
    int g    = lane >> 2;    // groupID
    int tg   = lane & 3;     // threadID in group

    int blk  = blockIdx.x / KSPLIT;
    int kc   = blockIdx.x - blk * KSPLIT;
    int row0 = blk * TM;
    int k0   = kc * KITEM;

    float acc[4][4];
#pragma unroll
    for (int n = 0; n < 4; n++)
#pragma unroll
        for (int i = 0; i < 4; i++) acc[n][i] = 0.f;

    const uint32_t aoff = (uint32_t)(warp * 16 + g) * 128 + tg * 4;
    const uint32_t boff = 16384u + (uint32_t)g * 128 + tg * 4;

#pragma unroll
    for (int p = 0; p < NSTAGES - 1; p++) {
        load_stage(dsm + p * STAGE_BYTES, adj, row0, k0 + p * 32, tid);
        asm volatile("cp.async.commit_group;\n" ::: "memory");
    }

    for (int c = 0; c < NCHUNK; c++) {
        asm volatile("cp.async.wait_group %0;\n" :: "n"(NSTAGES - 2) : "memory");
        __syncthreads();

        if (c + NSTAGES - 1 < NCHUNK)
            load_stage(dsm + ((c + NSTAGES - 1) % NSTAGES) * STAGE_BYTES, adj,
                       row0, k0 + (c + NSTAGES - 1) * 32, tid);
        asm volatile("cp.async.commit_group;\n" ::: "memory");

        const char* st = dsm + (c % NSTAGES) * STAGE_BYTES;
#pragma unroll
        for (int ks = 0; ks < 4; ks++) {
            uint32_t q0 = (uint32_t)(((2 * ks) ^ g) << 4);
            uint32_t q1 = (uint32_t)(((2 * ks + 1) ^ g) << 4);

            uint32_t a0 = *(const uint32_t*)(st + aoff + q0);
            uint32_t a2 = *(const uint32_t*)(st + aoff + q1);
            uint32_t a1 = *(const uint32_t*)(st + aoff + 1024 + q0);
            uint32_t a3 = *(const uint32_t*)(st + aoff + 1024 + q1);
#pragma unroll
            for (int nt = 0; nt < 4; nt++) {
                uint32_t b0 = *(const uint32_t*)(st + boff + nt * 1024 + q0);
                uint32_t b1 = *(const uint32_t*)(st + boff + nt * 1024 + q1);
                asm volatile(
                    "mma.sync.aligned.m16n8k8.row.col.f32.tf32.tf32.f32 "
                    "{%0,%1,%2,%3}, {%4,%5,%6,%7}, {%8,%9}, {%0,%1,%2,%3};\n"
                    : "+f"(acc[nt][0]), "+f"(acc[nt][1]),
                      "+f"(acc[nt][2]), "+f"(acc[nt][3])
                    : "r"(a0), "r"(a1), "r"(a2), "r"(a3), "r"(b0), "r"(b1));
            }
        }
    }

    float* part = g_part + (long long)kc * (NN * HID);
    int r_lo = row0 + warp * 16 + g;
    int r_hi = r_lo + 8;
#pragma unroll
    for (int nt = 0; nt < 4; nt++) {
        int colb = nt * 8 + 2 * tg;
        if (r_lo < NN)
            *(float2*)(part + (long long)r_lo * HID + colb) =
                make_float2(acc[nt][0], acc[nt][1]);
        if (r_hi < NN)
            *(float2*)(part + (long long)r_hi * HID + colb) =
                make_float2(acc[nt][2], acc[nt][3]);
    }
}

// ---------------------------------------------------------------------------
// Kernel 3: out = relu(sum_kc part[kc] + b)
// ---------------------------------------------------------------------------
__global__ void reduce_relu_kernel(float* __restrict__ out,
                                   const float* __restrict__ b) {
    int i4 = blockIdx.x * blockDim.x + threadIdx.x;
    if (i4 >= NN * HID / 4) return;
    const float4* p = (const float4*)g_part;
    float4 s = ((const float4*)b)[i4 & 7];
#pragma unroll
    for (int kc = 0; kc < KSPLIT; kc++) {
        float4 v = p[(long long)kc * (NN * HID / 4) + i4];
        s.x += v.x; s.y += v.y; s.z += v.z; s.w += v.w;
    }
    float4 r;
    r.x = fmaxf(s.x, 0.f);
    r.y = fmaxf(s.y, 0.f);
    r.z = fmaxf(s.z, 0.f);
    r.w = fmaxf(s.w, 0.f);
    ((float4*)out)[i4] = r;
}

// ---------------------------------------------------------------------------
extern "C" void kernel_launch(void* const* d_in, const int* in_sizes, int n_in,
                              void* d_out, int out_size) {
    (void)in_sizes; (void)n_in; (void)out_size;
    const float* t     = (const float*)d_in[0];
    const float* z     = (const float*)d_in[1];
    const float* adj   = (const float*)d_in[2];
    const float* treat = (const float*)d_in[3];
    const float* W     = (const float*)d_in[4];
    const float* b     = (const float*)d_in[5];
    float* out = (float*)d_out;

    cudaFuncSetAttribute(gemm_mma_kernel,
                         cudaFuncAttributeMaxDynamicSharedMemorySize, SMEM_REQ);

    support_kernel<<<NN / 32, 256>>>(t, z, treat, W);
    gemm_mma_kernel<<<NITEMS, 256, SMEM_REQ>>>(adj);
    reduce_relu_kernel<<<(NN * HID / 4 + 255) / 256, 256>>>(out, b);
}